// round 9
// baseline (speedup 1.0000x reference)
#include <cuda_runtime.h>
#include <cuda_bf16.h>
#include <cstdint>

// ============================================================================
// ModularLinear on GB300 — base-arch build (mma.sync HMMA.16816 bf16, fp32
// acc, 3-term hi/lo split). R9: smem-crossbar relief via TILE 128x256 with
// 2x4 warp layout (warp tile 64x64, 128 acc regs). 320 threads (256 consumer
// + 64 producer) to fit 204 regs/thread. 2-stage 96KB ring.
//
//   out[t, b, kk*1024 + o] = sum_i x[t, b, i] * w[sel[b,kk], o, i]
//   16 independent GEMMs of 2048 x 1024 x 1024 (fp32).
// ============================================================================

#define T_DIM   2048
#define B_DIM   8
#define IN_DIM  1024
#define OUT_DIM 1024
#define K_SEL   2

#define TILE_M  128
#define TILE_N  256
#define KC      64                         // K-chunk (fp32 elements)
#define NCHUNK  (IN_DIM / KC)              // 16
#define THREADS 320                        // 256 consumer + 64 producer
#define NSTG    2

// bf16 tiles, 128B rows, SW128-swizzled
#define AT_BYTES    (TILE_M * KC * 2)      // 16384 (Ah or Al)
#define BT_BYTES    (TILE_N * KC * 2)      // 32768 (Bh or Bl)
#define OFF_AH      0
#define OFF_AL      AT_BYTES               // 16384
#define OFF_BH      (2 * AT_BYTES)         // 32768
#define OFF_BL      (2 * AT_BYTES + BT_BYTES)  // 65536
#define STAGE_BYTES (2 * AT_BYTES + 2 * BT_BYTES)  // 98304
#define SMEM_TOTAL  (NSTG * STAGE_BYTES)   // 196608

// ---------------------------------------------------------------------------
// PTX helpers (base-arch only)
// ---------------------------------------------------------------------------
__device__ __forceinline__ uint32_t smem_u32(const void* p) {
    uint32_t a;
    asm("{ .reg .u64 t; cvta.to.shared.u64 t, %1; cvt.u32.u64 %0, t; }"
        : "=r"(a) : "l"(p));
    return a;
}

#define BAR_SYNC(id)   asm volatile("bar.sync %0, %1;"   :: "r"(id), "n"(THREADS) : "memory")
#define BAR_ARRIVE(id) asm volatile("bar.arrive %0, %1;" :: "r"(id), "n"(THREADS) : "memory")

__device__ __forceinline__ void ldsm4(uint32_t* r, uint32_t addr) {
    asm volatile("ldmatrix.sync.aligned.m8n8.x4.shared.b16 {%0,%1,%2,%3}, [%4];"
                 : "=r"(r[0]), "=r"(r[1]), "=r"(r[2]), "=r"(r[3])
                 : "r"(addr));
}

// D += A * B  (m16n8k16, bf16 in, fp32 acc)
__device__ __forceinline__ void mma16816(float* c, const uint32_t* a,
                                         const uint32_t* b) {
    asm volatile(
        "mma.sync.aligned.m16n8k16.row.col.f32.bf16.bf16.f32 "
        "{%0,%1,%2,%3}, {%4,%5,%6,%7}, {%8,%9}, {%0,%1,%2,%3};"
        : "+f"(c[0]), "+f"(c[1]), "+f"(c[2]), "+f"(c[3])
        : "r"(a[0]), "r"(a[1]), "r"(a[2]), "r"(a[3]),
          "r"(b[0]), "r"(b[1]));
}

// SW128 swizzle for 128B rows: bits[6:4] ^= bits[9:7]
__device__ __forceinline__ uint32_t sw128(uint32_t bo) {
    return bo ^ ((bo >> 3) & 0x70);
}

// split 8 consecutive fp32 (two uint4) into hi uint4 + lo uint4 (bf16x2 x4)
__device__ __forceinline__ void split_oct(uint4 u0, uint4 u1,
                                          uint4& hi, uint4& lo) {
    hi.x = __byte_perm(u0.x, u0.y, 0x7632);
    hi.y = __byte_perm(u0.z, u0.w, 0x7632);
    hi.z = __byte_perm(u1.x, u1.y, 0x7632);
    hi.w = __byte_perm(u1.z, u1.w, 0x7632);
    float l0 = __uint_as_float(u0.x) - __uint_as_float(u0.x & 0xFFFF0000u);
    float l1 = __uint_as_float(u0.y) - __uint_as_float(u0.y & 0xFFFF0000u);
    float l2 = __uint_as_float(u0.z) - __uint_as_float(u0.z & 0xFFFF0000u);
    float l3 = __uint_as_float(u0.w) - __uint_as_float(u0.w & 0xFFFF0000u);
    float l4 = __uint_as_float(u1.x) - __uint_as_float(u1.x & 0xFFFF0000u);
    float l5 = __uint_as_float(u1.y) - __uint_as_float(u1.y & 0xFFFF0000u);
    float l6 = __uint_as_float(u1.z) - __uint_as_float(u1.z & 0xFFFF0000u);
    float l7 = __uint_as_float(u1.w) - __uint_as_float(u1.w & 0xFFFF0000u);
    __nv_bfloat162 p0 = __float22bfloat162_rn(make_float2(l0, l1));
    __nv_bfloat162 p1 = __float22bfloat162_rn(make_float2(l2, l3));
    __nv_bfloat162 p2 = __float22bfloat162_rn(make_float2(l4, l5));
    __nv_bfloat162 p3 = __float22bfloat162_rn(make_float2(l6, l7));
    lo.x = *reinterpret_cast<uint32_t*>(&p0);
    lo.y = *reinterpret_cast<uint32_t*>(&p1);
    lo.z = *reinterpret_cast<uint32_t*>(&p2);
    lo.w = *reinterpret_cast<uint32_t*>(&p3);
}

// ============================================================================
// Kernel
// ============================================================================
__global__ void __launch_bounds__(THREADS, 1)
modlin_kernel(const float* __restrict__ x, const int* __restrict__ sel,
              const float* __restrict__ w, float* __restrict__ out)
{
    extern __shared__ char smem[];
    const int tid = threadIdx.x;
    const int wid = tid >> 5;
    const int lid = tid & 31;

    const int nt_blk = blockIdx.x;            // 0..3
    const int mt_blk = blockIdx.y;            // 0..15
    const int pi     = blockIdx.z;            // 0..15  (b,k) pair
    const int b  = pi >> 1;
    const int kk = pi & 1;
    const int m0 = mt_blk * TILE_M;
    const int n0 = nt_blk * TILE_N;

    const int e = sel[b * K_SEL + kk];

    const float* Abase = x + (((size_t)m0 * B_DIM + b) << 10);         // row stride B*IN
    const float* Bbase = w + ((((size_t)e << 10) + (size_t)n0) << 10); // row stride IN

    const uint32_t smem_base = smem_u32(smem);

    if (wid >= 8) {
        // ====================== PRODUCER (warps 8-9) ========================
        const int pid = tid - 256;             // 0..63
        int s = 0;
        for (int c = 0; c < NCHUNK; ++c) {
            if (c >= NSTG) BAR_SYNC(3 + s);    // wait stage empty

            const int kbase = c * KC;
            char* st = smem + s * STAGE_BYTES;

            // A tile: 128 x 64 = 1024 octs -> 16/thread, 2 batches of 8
            #pragma unroll
            for (int batch = 0; batch < 2; ++batch) {
                uint4 v[16];
                #pragma unroll
                for (int p = 0; p < 8; ++p) {
                    int g = pid + (batch * 8 + p) * 64;
                    int row = g >> 3, oct = g & 7;
                    const float* src =
                        Abase + (size_t)row * (B_DIM * IN_DIM) + kbase + oct * 8;
                    v[2 * p]     = *reinterpret_cast<const uint4*>(src);
                    v[2 * p + 1] = *reinterpret_cast<const uint4*>(src + 4);
                }
                #pragma unroll
                for (int p = 0; p < 8; ++p) {
                    int g = pid + (batch * 8 + p) * 64;
                    int row = g >> 3, oct = g & 7;
                    uint4 hi, lo;
                    split_oct(v[2 * p], v[2 * p + 1], hi, lo);
                    uint32_t sw = sw128((uint32_t)(row * 128 + oct * 16));
                    *reinterpret_cast<uint4*>(st + OFF_AH + sw) = hi;
                    *reinterpret_cast<uint4*>(st + OFF_AL + sw) = lo;
                }
            }
            // B tile: 256 x 64 = 2048 octs -> 32/thread, 4 batches of 8
            #pragma unroll
            for (int batch = 0; batch < 4; ++batch) {
                uint4 v[16];
                #pragma unroll
                for (int p = 0; p < 8; ++p) {
                    int g = pid + (batch * 8 + p) * 64;
                    int row = g >> 3, oct = g & 7;
                    const float* src =
                        Bbase + (size_t)row * IN_DIM + kbase + oct * 8;
                    v[2 * p]     = *reinterpret_cast<const uint4*>(src);
                    v[2 * p + 1] = *reinterpret_cast<const uint4*>(src + 4);
                }
                #pragma unroll
                for (int p = 0; p < 8; ++p) {
                    int g = pid + (batch * 8 + p) * 64;
                    int row = g >> 3, oct = g & 7;
                    uint4 hi, lo;
                    split_oct(v[2 * p], v[2 * p + 1], hi, lo);
                    uint32_t sw = sw128((uint32_t)(row * 128 + oct * 16));
                    *reinterpret_cast<uint4*>(st + OFF_BH + sw) = hi;
                    *reinterpret_cast<uint4*>(st + OFF_BL + sw) = lo;
                }
            }
            BAR_ARRIVE(1 + s);                 // stage full
            s ^= 1;
        }
        return;
    }

    // ======================== CONSUMER (warps 0-7) ==========================
    // 2 (m) x 4 (n) warp layout; warp tile 64 x 64
    const int warp_m = (wid & 1) * 64;
    const int warp_n = (wid >> 1) * 64;
    const int tile = lid >> 3;                 // ldmatrix sub-tile 0..3
    const int trow = lid & 7;
    const int qr = lid >> 2;                   // mma fragment row
    const int qc = lid & 3;

    // ldsm base offsets; k16 variants derived by XOR with (k16<<5).
    // Identity: sw128(row*128 + kb) = row*128 + (kb ^ ((row&7)<<4)), kb<128.
    uint32_t aBase[4], bBase[4];
    #pragma unroll
    for (int mt = 0; mt < 4; ++mt) {
        int row  = warp_m + mt * 16 + ((tile & 1) << 3) + trow;
        int tsel = (tile >> 1) << 4;
        aBase[mt] = (uint32_t)(row * 128 + (tsel ^ ((row & 7) << 4)));
    }
    #pragma unroll
    for (int nt2 = 0; nt2 < 4; ++nt2) {
        int row  = warp_n + nt2 * 16 + ((tile >> 1) << 3) + trow;
        int tsel = (tile & 1) << 4;
        bBase[nt2] = (uint32_t)(row * 128 + (tsel ^ ((row & 7) << 4)));
    }

    float acc[4][8][4];
    #pragma unroll
    for (int i = 0; i < 4; ++i)
        #pragma unroll
        for (int j = 0; j < 8; ++j)
            #pragma unroll
            for (int v = 0; v < 4; ++v) acc[i][j][v] = 0.0f;

    int s = 0;
    for (int c = 0; c < NCHUNK; ++c) {
        BAR_SYNC(1 + s);                       // wait stage full

        const uint32_t stB = smem_base + s * STAGE_BYTES;
        const uint32_t ahB = stB + OFF_AH;
        const uint32_t alB = stB + OFF_AL;
        const uint32_t bhB = stB + OFF_BH;
        const uint32_t blB = stB + OFF_BL;

        #pragma unroll
        for (int k16 = 0; k16 < 4; ++k16) {
            const uint32_t kx = (uint32_t)(k16 << 5);
            uint32_t ah[4][4], al[4][4], bh[8][2], bl[8][2];

            // hi fragments -> hh MMAs
            #pragma unroll
            for (int mt = 0; mt < 4; ++mt)
                ldsm4(ah[mt], ahB + (aBase[mt] ^ kx));
            #pragma unroll
            for (int nt2 = 0; nt2 < 4; ++nt2) {
                uint32_t r[4];
                ldsm4(r, bhB + (bBase[nt2] ^ kx));
                bh[2 * nt2][0] = r[0]; bh[2 * nt2][1] = r[1];
                bh[2 * nt2 + 1][0] = r[2]; bh[2 * nt2 + 1][1] = r[3];
            }
            #pragma unroll
            for (int mt = 0; mt < 4; ++mt)
                #pragma unroll
                for (int nt = 0; nt < 8; ++nt)
                    mma16816(acc[mt][nt], ah[mt], bh[nt]);

            // al fragments -> lh MMAs (bh still live, dies after)
            #pragma unroll
            for (int mt = 0; mt < 4; ++mt)
                ldsm4(al[mt], alB + (aBase[mt] ^ kx));
            #pragma unroll
            for (int mt = 0; mt < 4; ++mt)
                #pragma unroll
                for (int nt = 0; nt < 8; ++nt)
                    mma16816(acc[mt][nt], al[mt], bh[nt]);

            // bl fragments -> hl MMAs (reuses bh registers)
            #pragma unroll
            for (int nt2 = 0; nt2 < 4; ++nt2) {
                uint32_t r[4];
                ldsm4(r, blB + (bBase[nt2] ^ kx));
                bl[2 * nt2][0] = r[0]; bl[2 * nt2][1] = r[1];
                bl[2 * nt2 + 1][0] = r[2]; bl[2 * nt2 + 1][1] = r[3];
            }
            // early release: last smem read of this stage just issued
            if (k16 == 3) BAR_ARRIVE(3 + s);
            #pragma unroll
            for (int mt = 0; mt < 4; ++mt)
                #pragma unroll
                for (int nt = 0; nt < 8; ++nt)
                    mma16816(acc[mt][nt], ah[mt], bl[nt]);
        }
        s ^= 1;
    }

    // ---- epilogue: direct fp32 stores ----
    const size_t row_stride = (size_t)B_DIM * K_SEL * OUT_DIM;   // 16384 floats
    #pragma unroll
    for (int mt = 0; mt < 4; ++mt) {
        const int t = m0 + warp_m + mt * 16 + qr;
        float* orow = out + (size_t)t * row_stride
                          + ((size_t)b * K_SEL + kk) * OUT_DIM
                          + n0 + warp_n + qc * 2;
        #pragma unroll
        for (int nt = 0; nt < 8; ++nt) {
            float2 v0 = make_float2(acc[mt][nt][0], acc[mt][nt][1]);
            float2 v1 = make_float2(acc[mt][nt][2], acc[mt][nt][3]);
            *reinterpret_cast<float2*>(orow + nt * 8) = v0;
            *reinterpret_cast<float2*>(orow + nt * 8 + 8 * row_stride) = v1;
        }
    }
}

// ============================================================================
// Launch
// ============================================================================
extern "C" void kernel_launch(void* const* d_in, const int* in_sizes, int n_in,
                              void* d_out, int out_size) {
    (void)in_sizes; (void)n_in; (void)out_size;
    const float* x   = (const float*)d_in[0];
    const int*   sel = (const int*)d_in[1];
    const float* w   = (const float*)d_in[2];
    float*       out = (float*)d_out;

    cudaFuncSetAttribute(modlin_kernel,
                         cudaFuncAttributeMaxDynamicSharedMemorySize, SMEM_TOTAL);

    dim3 grid(OUT_DIM / TILE_N,            // 4
              T_DIM / TILE_M,              // 16
              B_DIM * K_SEL);              // 16
    modlin_kernel<<<grid, THREADS, SMEM_TOTAL>>>(x, sel, w, out);
}

// round 10
// speedup vs baseline: 1.0342x; 1.0342x over previous
#include <cuda_runtime.h>
#include <cuda_bf16.h>
#include <cstdint>

// ============================================================================
// ModularLinear on GB300 — base-arch build (mma.sync HMMA.16816 bf16, fp32
// acc, 3-term hi/lo split). R10: R8 skeleton (TILE 128x128, KC=64, NSTG=3)
// + anti-phase k16 scheduling between SMSP-sharing warps + ah/bh fragment
// double-buffering, enabled by 320 threads (reg cap 204).
//
//   out[t, b, kk*1024 + o] = sum_i x[t, b, i] * w[sel[b,kk], o, i]
//   16 independent GEMMs of 2048 x 1024 x 1024 (fp32).
// ============================================================================

#define T_DIM   2048
#define B_DIM   8
#define IN_DIM  1024
#define OUT_DIM 1024
#define K_SEL   2

#define TILE_M  128
#define TILE_N  128
#define KC      64                         // K-chunk (fp32 elements)
#define NCHUNK  (IN_DIM / KC)              // 16
#define THREADS 320                        // 256 consumer + 64 producer
#define NSTG    3

// bf16 tile: 128 rows x 64 bf16 (128B rows), SW128-swizzled -> 16KB
#define BF_TILE     (TILE_M * KC * 2)      // 16384
#define STAGE_BYTES (4 * BF_TILE)          // Ah, Al, Bh, Bl = 65536
#define SMEM_TOTAL  (NSTG * STAGE_BYTES)   // 196608

// ---------------------------------------------------------------------------
// PTX helpers (base-arch only)
// ---------------------------------------------------------------------------
__device__ __forceinline__ uint32_t smem_u32(const void* p) {
    uint32_t a;
    asm("{ .reg .u64 t; cvta.to.shared.u64 t, %1; cvt.u32.u64 %0, t; }"
        : "=r"(a) : "l"(p));
    return a;
}

#define BAR_SYNC(id)   asm volatile("bar.sync %0, %1;"   :: "r"(id), "n"(THREADS) : "memory")
#define BAR_ARRIVE(id) asm volatile("bar.arrive %0, %1;" :: "r"(id), "n"(THREADS) : "memory")

__device__ __forceinline__ void ldsm4(uint32_t* r, uint32_t addr) {
    asm volatile("ldmatrix.sync.aligned.m8n8.x4.shared.b16 {%0,%1,%2,%3}, [%4];"
                 : "=r"(r[0]), "=r"(r[1]), "=r"(r[2]), "=r"(r[3])
                 : "r"(addr));
}

// D += A * B  (m16n8k16, bf16 in, fp32 acc)
__device__ __forceinline__ void mma16816(float* c, const uint32_t* a,
                                         const uint32_t* b) {
    asm volatile(
        "mma.sync.aligned.m16n8k16.row.col.f32.bf16.bf16.f32 "
        "{%0,%1,%2,%3}, {%4,%5,%6,%7}, {%8,%9}, {%0,%1,%2,%3};"
        : "+f"(c[0]), "+f"(c[1]), "+f"(c[2]), "+f"(c[3])
        : "r"(a[0]), "r"(a[1]), "r"(a[2]), "r"(a[3]),
          "r"(b[0]), "r"(b[1]));
}

// SW128 swizzle for 128B rows: bits[6:4] ^= bits[9:7]
__device__ __forceinline__ uint32_t sw128(uint32_t bo) {
    return bo ^ ((bo >> 3) & 0x70);
}

// split 8 consecutive fp32 (two uint4) into hi uint4 + lo uint4 (bf16x2 x4)
__device__ __forceinline__ void split_oct(uint4 u0, uint4 u1,
                                          uint4& hi, uint4& lo) {
    hi.x = __byte_perm(u0.x, u0.y, 0x7632);
    hi.y = __byte_perm(u0.z, u0.w, 0x7632);
    hi.z = __byte_perm(u1.x, u1.y, 0x7632);
    hi.w = __byte_perm(u1.z, u1.w, 0x7632);
    float l0 = __uint_as_float(u0.x) - __uint_as_float(u0.x & 0xFFFF0000u);
    float l1 = __uint_as_float(u0.y) - __uint_as_float(u0.y & 0xFFFF0000u);
    float l2 = __uint_as_float(u0.z) - __uint_as_float(u0.z & 0xFFFF0000u);
    float l3 = __uint_as_float(u0.w) - __uint_as_float(u0.w & 0xFFFF0000u);
    float l4 = __uint_as_float(u1.x) - __uint_as_float(u1.x & 0xFFFF0000u);
    float l5 = __uint_as_float(u1.y) - __uint_as_float(u1.y & 0xFFFF0000u);
    float l6 = __uint_as_float(u1.z) - __uint_as_float(u1.z & 0xFFFF0000u);
    float l7 = __uint_as_float(u1.w) - __uint_as_float(u1.w & 0xFFFF0000u);
    __nv_bfloat162 p0 = __float22bfloat162_rn(make_float2(l0, l1));
    __nv_bfloat162 p1 = __float22bfloat162_rn(make_float2(l2, l3));
    __nv_bfloat162 p2 = __float22bfloat162_rn(make_float2(l4, l5));
    __nv_bfloat162 p3 = __float22bfloat162_rn(make_float2(l6, l7));
    lo.x = *reinterpret_cast<uint32_t*>(&p0);
    lo.y = *reinterpret_cast<uint32_t*>(&p1);
    lo.z = *reinterpret_cast<uint32_t*>(&p2);
    lo.w = *reinterpret_cast<uint32_t*>(&p3);
}

// ============================================================================
// Kernel
// ============================================================================
__global__ void __launch_bounds__(THREADS, 1)
modlin_kernel(const float* __restrict__ x, const int* __restrict__ sel,
              const float* __restrict__ w, float* __restrict__ out)
{
    extern __shared__ char smem[];
    const int tid = threadIdx.x;
    const int wid = tid >> 5;
    const int lid = tid & 31;

    const int nt_blk = blockIdx.x;            // 0..7
    const int mt_blk = blockIdx.y;            // 0..15
    const int pi     = blockIdx.z;            // 0..15  (b,k) pair
    const int b  = pi >> 1;
    const int kk = pi & 1;
    const int m0 = mt_blk * TILE_M;
    const int n0 = nt_blk * TILE_N;

    const int e = sel[b * K_SEL + kk];

    const float* Abase = x + (((size_t)m0 * B_DIM + b) << 10);         // row stride B*IN
    const float* Bbase = w + ((((size_t)e << 10) + (size_t)n0) << 10); // row stride IN

    const uint32_t smem_base = smem_u32(smem);

    if (wid >= 8) {
        // ====================== PRODUCER (warps 8-9) ========================
        const int pid = tid - 256;             // 0..63
        int s = 0;
        for (int c = 0; c < NCHUNK; ++c) {
            if (c >= NSTG) BAR_SYNC(4 + s);    // wait stage empty

            const int kbase = c * KC;
            char* st = smem + s * STAGE_BYTES;

            // A then B: each 128 rows x 64 elems = 1024 octs -> 16/thread
            #pragma unroll
            for (int half = 0; half < 2; ++half) {
                char* hiT = st + half * 2 * BF_TILE;
                #pragma unroll
                for (int batch = 0; batch < 2; ++batch) {
                    uint4 v[16];
                    #pragma unroll
                    for (int p = 0; p < 8; ++p) {
                        int g = pid + (batch * 8 + p) * 64;  // oct 0..1023
                        int row = g >> 3, oct = g & 7;
                        const float* src = half == 0
                            ? Abase + (size_t)row * (B_DIM * IN_DIM) + kbase + oct * 8
                            : Bbase + (size_t)row * IN_DIM + kbase + oct * 8;
                        v[2 * p]     = *reinterpret_cast<const uint4*>(src);
                        v[2 * p + 1] = *reinterpret_cast<const uint4*>(src + 4);
                    }
                    #pragma unroll
                    for (int p = 0; p < 8; ++p) {
                        int g = pid + (batch * 8 + p) * 64;
                        int row = g >> 3, oct = g & 7;
                        uint4 hi, lo;
                        split_oct(v[2 * p], v[2 * p + 1], hi, lo);
                        uint32_t sw = sw128((uint32_t)(row * 128 + oct * 16));
                        *reinterpret_cast<uint4*>(hiT + sw) = hi;
                        *reinterpret_cast<uint4*>(hiT + BF_TILE + sw) = lo;
                    }
                }
            }
            BAR_ARRIVE(1 + s);                 // stage full
            if (++s == NSTG) s = 0;
        }
        return;
    }

    // ======================== CONSUMER (warps 0-7) ==========================
    // 4 (m) x 2 (n) warp layout; warp tile 32 x 64 (proven R8 geometry)
    const int warp_m = (wid & 3) * 32;
    const int warp_n = (wid >> 2) * 64;
    const int tile = lid >> 3;                 // ldmatrix sub-tile 0..3
    const int trow = lid & 7;
    const int qr = lid >> 2;                   // mma fragment row
    const int qc = lid & 3;

    // Anti-phase: SMSP partner warps (wid parity) start 2 phases apart.
    const int kph0 = (wid & 1) << 1;

    // ldsm base offsets; k16 variant = base ^ (k16<<5).
    // Identity (validated R9): sw128(row*128+kb) = row*128 + (kb ^ ((row&7)<<4))
    uint32_t aBase[2], bBase[4];
    #pragma unroll
    for (int mt = 0; mt < 2; ++mt) {
        int row  = warp_m + mt * 16 + ((tile & 1) << 3) + trow;
        int tsel = (tile >> 1) << 4;
        aBase[mt] = (uint32_t)(row * 128 + (tsel ^ ((row & 7) << 4)));
    }
    #pragma unroll
    for (int nt2 = 0; nt2 < 4; ++nt2) {
        int row  = warp_n + nt2 * 16 + ((tile >> 1) << 3) + trow;
        int tsel = (tile & 1) << 4;
        bBase[nt2] = (uint32_t)(row * 128 + (tsel ^ ((row & 7) << 4)));
    }

    float acc[2][8][4];
    #pragma unroll
    for (int i = 0; i < 2; ++i)
        #pragma unroll
        for (int j = 0; j < 8; ++j)
            #pragma unroll
            for (int v = 0; v < 4; ++v) acc[i][j][v] = 0.0f;

    int s = 0;
    for (int c = 0; c < NCHUNK; ++c) {
        BAR_SYNC(1 + s);                       // wait stage full

        const uint32_t stB = smem_base + s * STAGE_BYTES;
        const uint32_t ahB = stB;
        const uint32_t alB = stB + BF_TILE;
        const uint32_t bhB = stB + 2 * BF_TILE;
        const uint32_t blB = stB + 3 * BF_TILE;

        // double-buffered hi fragments; al/bl single-buffered per phase
        uint32_t ah[2][2][4], bh[2][8][2], al[2][4], bl[8][2];

        // preload phase 0 (this warp's first phase)
        {
            const uint32_t kx = (uint32_t)(kph0 << 5);
            #pragma unroll
            for (int mt = 0; mt < 2; ++mt)
                ldsm4(ah[0][mt], ahB + (aBase[mt] ^ kx));
            #pragma unroll
            for (int nt2 = 0; nt2 < 4; ++nt2) {
                uint32_t r[4];
                ldsm4(r, bhB + (bBase[nt2] ^ kx));
                bh[0][2 * nt2][0] = r[0]; bh[0][2 * nt2][1] = r[1];
                bh[0][2 * nt2 + 1][0] = r[2]; bh[0][2 * nt2 + 1][1] = r[3];
            }
        }

        #pragma unroll
        for (int i = 0; i < 4; ++i) {
            const int cur = i & 1, nxt = cur ^ 1;
            const uint32_t kx  = (uint32_t)((((i + kph0) & 3)) << 5);
            const uint32_t kxn = (uint32_t)((((i + 1 + kph0) & 3)) << 5);

            // lo fragments for current phase
            #pragma unroll
            for (int mt = 0; mt < 2; ++mt)
                ldsm4(al[mt], alB + (aBase[mt] ^ kx));
            #pragma unroll
            for (int nt2 = 0; nt2 < 4; ++nt2) {
                uint32_t r[4];
                ldsm4(r, blB + (bBase[nt2] ^ kx));
                bl[2 * nt2][0] = r[0]; bl[2 * nt2][1] = r[1];
                bl[2 * nt2 + 1][0] = r[2]; bl[2 * nt2 + 1][1] = r[3];
            }
            // last smem read of this stage just issued -> release early
            if (i == 3) BAR_ARRIVE(4 + s);

            // hh MMAs
            #pragma unroll
            for (int mt = 0; mt < 2; ++mt)
                #pragma unroll
                for (int nt = 0; nt < 8; ++nt)
                    mma16816(acc[mt][nt], ah[cur][mt], bh[cur][nt]);

            // prefetch next phase hi fragments during MMA drain
            if (i < 3) {
                #pragma unroll
                for (int mt = 0; mt < 2; ++mt)
                    ldsm4(ah[nxt][mt], ahB + (aBase[mt] ^ kxn));
                #pragma unroll
                for (int nt2 = 0; nt2 < 4; ++nt2) {
                    uint32_t r[4];
                    ldsm4(r, bhB + (bBase[nt2] ^ kxn));
                    bh[nxt][2 * nt2][0] = r[0]; bh[nxt][2 * nt2][1] = r[1];
                    bh[nxt][2 * nt2 + 1][0] = r[2]; bh[nxt][2 * nt2 + 1][1] = r[3];
                }
            }

            // hl + lh MMAs
            #pragma unroll
            for (int mt = 0; mt < 2; ++mt)
                #pragma unroll
                for (int nt = 0; nt < 8; ++nt)
                    mma16816(acc[mt][nt], ah[cur][mt], bl[nt]);
            #pragma unroll
            for (int mt = 0; mt < 2; ++mt)
                #pragma unroll
                for (int nt = 0; nt < 8; ++nt)
                    mma16816(acc[mt][nt], al[mt], bh[cur][nt]);
        }
        if (++s == NSTG) s = 0;
    }

    // ---- epilogue: direct fp32 stores ----
    const size_t row_stride = (size_t)B_DIM * K_SEL * OUT_DIM;   // 16384 floats
    #pragma unroll
    for (int mt = 0; mt < 2; ++mt) {
        const int t = m0 + warp_m + mt * 16 + qr;
        float* orow = out + (size_t)t * row_stride
                          + ((size_t)b * K_SEL + kk) * OUT_DIM
                          + n0 + warp_n + qc * 2;
        #pragma unroll
        for (int nt = 0; nt < 8; ++nt) {
            float2 v0 = make_float2(acc[mt][nt][0], acc[mt][nt][1]);
            float2 v1 = make_float2(acc[mt][nt][2], acc[mt][nt][3]);
            *reinterpret_cast<float2*>(orow + nt * 8) = v0;
            *reinterpret_cast<float2*>(orow + nt * 8 + 8 * row_stride) = v1;
        }
    }
}

// ============================================================================
// Launch
// ============================================================================
extern "C" void kernel_launch(void* const* d_in, const int* in_sizes, int n_in,
                              void* d_out, int out_size) {
    (void)in_sizes; (void)n_in; (void)out_size;
    const float* x   = (const float*)d_in[0];
    const int*   sel = (const int*)d_in[1];
    const float* w   = (const float*)d_in[2];
    float*       out = (float*)d_out;

    cudaFuncSetAttribute(modlin_kernel,
                         cudaFuncAttributeMaxDynamicSharedMemorySize, SMEM_TOTAL);

    dim3 grid(OUT_DIM / TILE_N,            // 8
              T_DIM / TILE_M,              // 16
              B_DIM * K_SEL);              // 16
    modlin_kernel<<<grid, THREADS, SMEM_TOTAL>>>(x, sel, w, out);
}